// round 6
// baseline (speedup 1.0000x reference)
#include <cuda_runtime.h>
#include <math.h>

// Problem constants (fixed by the dataset)
#define Bq 2
#define Lq 32
#define Eq 256
#define Hq 4096
#define Gq 16
#define Rq 64
#define H4 1024   // Hq/4 (float4 units)

// Scratch (device globals; no allocation in kernel_launch)
__device__ float g_wkq[Hq];            // Wk^T @ layer_query        [H]
__device__ float g_lscore[Bq*Lq];      // layer scores (accum)      [B,L]
__device__ float g_lw[Bq*Lq];          // layer softmax weights     [B,L]
__device__ float g_ek[Bq*Eq*Hq];       // layer-weighted k          [B,E,H]  8MB
__device__ float g_ev[Bq*Eq*Hq];       // layer-weighted v          [B,E,H]  8MB
__device__ float g_qkh[Gq*Hq];         // inv_sqrt_r * q @ Wk       [G,H]
__device__ float g_scores[Bq*Gq*Eq];   // cross-attn logits         [B,G,E]
__device__ float g_aw[Bq*Eq];          // mean_g attn               [B,E]
__device__ float g_sh[Bq*Hq];          // Σ_e aw*ev (accum)         [B,H]

// ---------------------------------------------------------------------------
// K1: wkq[h] = Σ_r Wk[r,h]*lq[r]; also zero the accumulators.
// grid(17,1,1) x 256
__global__ void k_prep(const float* __restrict__ Wk, const float* __restrict__ lq) {
    __shared__ float slq[Rq];
    int tid = threadIdx.x;
    if (blockIdx.x < 16) {
        if (tid < Rq) slq[tid] = lq[tid];
        __syncthreads();
        int h = blockIdx.x * 256 + tid;
        float s = 0.f;
        #pragma unroll
        for (int r = 0; r < Rq; ++r) s += Wk[r * Hq + h] * slq[r];
        g_wkq[h] = s;
    } else {
        if (tid < Bq * Lq) g_lscore[tid] = 0.f;
        for (int i = tid; i < Bq * Hq; i += 256) g_sh[i] = 0.f;
    }
}

// ---------------------------------------------------------------------------
// K2: layer score partials: Σ_{e,h} evicted_k[b,l,e,h]*wkq[h]  (268 MB stream)
// grid(16, L, B) x 256; each block handles 16 e-rows.
__global__ void k_lscore(const float4* __restrict__ evk4) {
    int tid = threadIdx.x;
    int e0 = blockIdx.x * 16;
    int l  = blockIdx.y;
    int b  = blockIdx.z;
    size_t base4 = ((size_t)((b * Lq + l) * Eq + e0)) * H4;
    const float4* wkq4 = (const float4*)g_wkq;
    float acc = 0.f;
    #pragma unroll 4
    for (int i = 0; i < 64; ++i) {
        int idx = i * 256 + tid;           // 0..16383 (16 rows x 1024 f4)
        float4 d = evk4[base4 + idx];
        float4 w = wkq4[idx & (H4 - 1)];
        acc += d.x * w.x + d.y * w.y + d.z * w.z + d.w * w.w;
    }
    __shared__ float red[256];
    red[tid] = acc; __syncthreads();
    #pragma unroll
    for (int s = 128; s > 0; s >>= 1) {
        if (tid < s) red[tid] += red[tid + s];
        __syncthreads();
    }
    if (tid == 0) atomicAdd(&g_lscore[b * Lq + l], red[0]);
}

// ---------------------------------------------------------------------------
// K3: softmax over L per b. <<<1,64>>> : warp 0 -> b=0, warp 1 -> b=1.
__global__ void k_softL() {
    int tid = threadIdx.x;
    // scale = inv_sqrt_r / (LAYER_TEMP * E) = (1/8)/256
    float s = g_lscore[tid] * (1.0f / 2048.0f);
    float m = s;
    #pragma unroll
    for (int o = 16; o; o >>= 1) m = fmaxf(m, __shfl_xor_sync(0xffffffffu, m, o));
    float e = expf(s - m);
    float sum = e;
    #pragma unroll
    for (int o = 16; o; o >>= 1) sum += __shfl_xor_sync(0xffffffffu, sum, o);
    g_lw[tid] = e / sum;
}

// ---------------------------------------------------------------------------
// K4: ek/ev[b,e,h] = Σ_l w[b,l]*input[b,l,e,h]   (536 MB stream, 16 MB write)
// grid(4, E, 4) x 256; z<2 -> k (b=z), z>=2 -> v (b=z-2).
__global__ void k_weight(const float4* __restrict__ evk4,
                         const float4* __restrict__ evv4) {
    __shared__ float sw[Lq];
    int tid = threadIdx.x;
    int hc  = blockIdx.x;     // 0..3 (1024-float chunk of H)
    int e   = blockIdx.y;     // 0..255
    int z   = blockIdx.z;     // 0..3
    int b   = z & 1;
    const float4* in = (z < 2) ? evk4 : evv4;
    float4* outp = (float4*)((z < 2) ? g_ek : g_ev);
    if (tid < Lq) sw[tid] = g_lw[b * Lq + tid];
    __syncthreads();
    int off = hc * 256 + tid;                 // f4 offset within H
    const float4* p = in + ((size_t)(b * Lq) * Eq + e) * H4 + off;
    const size_t lstride = (size_t)Eq * H4;   // stride between l slices (f4)
    float4 acc = make_float4(0.f, 0.f, 0.f, 0.f);
    #pragma unroll
    for (int l = 0; l < Lq; ++l) {
        float4 d = p[l * lstride];
        float w = sw[l];
        acc.x += w * d.x; acc.y += w * d.y; acc.z += w * d.z; acc.w += w * d.w;
    }
    outp[((size_t)(b * Eq + e)) * H4 + off] = acc;
}

// ---------------------------------------------------------------------------
// K5: q[g,r] = Σ_h gq[g,h]*Wq[r,h];  qk[g,h] = inv_sqrt_r * Σ_r q[g,r]*Wk[r,h]
// grid(G) x 256.
__global__ void k_qk(const float4* __restrict__ gq4,
                     const float4* __restrict__ wq4,
                     const float4* __restrict__ wk4) {
    int g = blockIdx.x;
    int tid = threadIdx.x;
    int r = tid & 63, part = tid >> 6;
    __shared__ float red[256];
    __shared__ float sq[Rq];
    // phase 1: q[g,r]
    float s = 0.f;
    int base = part * 256;
    for (int i = 0; i < 256; ++i) {
        float4 a = gq4[g * H4 + base + i];
        float4 w = wq4[r * H4 + base + i];
        s += a.x * w.x + a.y * w.y + a.z * w.z + a.w * w.w;
    }
    red[tid] = s; __syncthreads();
    if (tid < Rq) sq[tid] = red[tid] + red[tid + 64] + red[tid + 128] + red[tid + 192];
    __syncthreads();
    // phase 2: qk[g,h], vectorized over h
    float4* qk4 = (float4*)g_qkh;
    #pragma unroll
    for (int j = 0; j < 4; ++j) {
        int h4 = j * 256 + tid;               // f4 index within H
        float4 v = make_float4(0.f, 0.f, 0.f, 0.f);
        #pragma unroll 8
        for (int rr = 0; rr < Rq; ++rr) {
            float4 w = wk4[rr * H4 + h4];
            float qv = sq[rr];
            v.x += qv * w.x; v.y += qv * w.y; v.z += qv * w.z; v.w += qv * w.w;
        }
        v.x *= 0.125f; v.y *= 0.125f; v.z *= 0.125f; v.w *= 0.125f;  // inv_sqrt_r
        qk4[g * H4 + h4] = v;
    }
}

// ---------------------------------------------------------------------------
// K6: scores[b,g,e] = Σ_h ek[b,e,h]*qk[g,h].  grid(E/4, B) x 256.
__global__ __launch_bounds__(256) void k_scores() {
    int tid = threadIdx.x;
    int e0 = blockIdx.x * 4;
    int b  = blockIdx.y;
    const float4* ek4 = (const float4*)g_ek;
    const float4* qk4 = (const float4*)g_qkh;
    float acc[4][16];
    #pragma unroll
    for (int j = 0; j < 4; ++j)
        #pragma unroll
        for (int g = 0; g < 16; ++g) acc[j][g] = 0.f;
    size_t rowb = ((size_t)(b * Eq + e0)) * H4;
    #pragma unroll
    for (int i = 0; i < 4; ++i) {
        int off = i * 256 + tid;
        float4 ev[4];
        #pragma unroll
        for (int j = 0; j < 4; ++j) ev[j] = ek4[rowb + j * H4 + off];
        #pragma unroll
        for (int g = 0; g < 16; ++g) {
            float4 q = qk4[g * H4 + off];
            #pragma unroll
            for (int j = 0; j < 4; ++j)
                acc[j][g] += ev[j].x * q.x + ev[j].y * q.y + ev[j].z * q.z + ev[j].w * q.w;
        }
    }
    __shared__ float sbuf[64 * 8];
    int lane = tid & 31, warp = tid >> 5;
    #pragma unroll
    for (int j = 0; j < 4; ++j)
        #pragma unroll
        for (int g = 0; g < 16; ++g) {
            float v = acc[j][g];
            #pragma unroll
            for (int o = 16; o; o >>= 1) v += __shfl_down_sync(0xffffffffu, v, o);
            if (lane == 0) sbuf[(j * 16 + g) * 8 + warp] = v;
        }
    __syncthreads();
    if (tid < 64) {
        int j = tid >> 4, g = tid & 15;
        float s = 0.f;
        #pragma unroll
        for (int w = 0; w < 8; ++w) s += sbuf[tid * 8 + w];
        g_scores[(b * Gq + g) * Eq + e0 + j] = s;
    }
}

// ---------------------------------------------------------------------------
// K7: softmax over E per (b,g); aw[b,e] = mean_g attn.  grid(B) x 256.
__global__ void k_attn() {
    int tid = threadIdx.x;        // == e
    int b = blockIdx.x;
    __shared__ float red[256];
    float awacc = 0.f;
    for (int g = 0; g < Gq; ++g) {
        float s = g_scores[(b * Gq + g) * Eq + tid];
        red[tid] = s; __syncthreads();
        #pragma unroll
        for (int o = 128; o; o >>= 1) {
            if (tid < o) red[tid] = fmaxf(red[tid], red[tid + o]);
            __syncthreads();
        }
        float m = red[0]; __syncthreads();
        float e = expf(s - m);
        red[tid] = e; __syncthreads();
        #pragma unroll
        for (int o = 128; o; o >>= 1) {
            if (tid < o) red[tid] += red[tid + o];
            __syncthreads();
        }
        float sum = red[0]; __syncthreads();
        awacc += e / sum;
    }
    g_aw[b * Eq + tid] = awacc * (1.0f / (float)Gq);
}

// ---------------------------------------------------------------------------
// K8: sh[b,h] += Σ_e aw[b,e]*ev[b,e,h]  (8 MB stream). grid(8,4,B) x 256.
__global__ void k_sh() {
    __shared__ float sa[32];
    int tid = threadIdx.x;
    int e0 = blockIdx.x * 32;
    int hc = blockIdx.y;
    int b  = blockIdx.z;
    if (tid < 32) sa[tid] = g_aw[b * Eq + e0 + tid];
    __syncthreads();
    const float4* ev4 = (const float4*)g_ev;
    int off = hc * 256 + tid;
    float4 acc = make_float4(0.f, 0.f, 0.f, 0.f);
    #pragma unroll
    for (int e = 0; e < 32; ++e) {
        float4 d = ev4[((size_t)(b * Eq + e0 + e)) * H4 + off];
        float a = sa[e];
        acc.x += a * d.x; acc.y += a * d.y; acc.z += a * d.z; acc.w += a * d.w;
    }
    float* shp = &g_sh[b * Hq + off * 4];
    atomicAdd(shp + 0, acc.x);
    atomicAdd(shp + 1, acc.y);
    atomicAdd(shp + 2, acc.z);
    atomicAdd(shp + 3, acc.w);
}

// ---------------------------------------------------------------------------
// K9: s_new[b,r] = Σ_h sh[b,h]*Wv[r,h]; gated update + norm clamp.
// grid(B) x 512.
__global__ void k_final(const float* __restrict__ state,
                        const float4* __restrict__ wv4,
                        const int* __restrict__ tok,
                        float* __restrict__ out) {
    int tid = threadIdx.x;        // 0..511
    int b = blockIdx.x;
    int r = tid & 63, part = tid >> 6;   // 8 parts of 128 f4
    const float4* sh4 = (const float4*)g_sh;
    float s = 0.f;
    int base = part * 128;
    for (int i = 0; i < 128; ++i) {
        float4 a = sh4[b * H4 + base + i];
        float4 w = wv4[r * H4 + base + i];
        s += a.x * w.x + a.y * w.y + a.z * w.z + a.w * w.w;
    }
    __shared__ float red[512];
    __shared__ float snew[64], uvec[64];
    __shared__ float rr[3 * 64];
    __shared__ float gate_s, scale_s;
    red[tid] = s; __syncthreads();
    if (tid < 64) {
        float sn = 0.f;
        #pragma unroll
        for (int p = 0; p < 8; ++p) sn += red[tid + p * 64];
        snew[tid] = sn;
        float pv = state[b * Rq + tid];
        rr[tid] = pv * pv; rr[64 + tid] = sn * sn; rr[128 + tid] = pv * sn;
    }
    __syncthreads();
    if (tid == 0) {
        float pp = 0.f, ss = 0.f, ps = 0.f;
        for (int i = 0; i < 64; ++i) { pp += rr[i]; ss += rr[64 + i]; ps += rr[128 + i]; }
        float np = fmaxf(sqrtf(pp), 1e-6f);
        float ns = fmaxf(sqrtf(ss), 1e-6f);
        float sim = ps / (np * ns);
        sim = fminf(1.f, fmaxf(-1.f, sim));
        float gate = 0.1f + 0.8f * 0.5f * (sim + 1.f);
        float evd = fminf(1.f, (float)tok[0] * (1.0f / 256.0f));
        gate_s = gate * evd;
    }
    __syncthreads();
    if (tid < 64) {
        float g = gate_s;
        float u = (1.f - g) * state[b * Rq + tid] + g * snew[tid];
        uvec[tid] = u;
        rr[tid] = u * u;
    }
    __syncthreads();
    if (tid == 0) {
        float nn = 0.f;
        for (int i = 0; i < 64; ++i) nn += rr[i];
        float n = sqrtf(nn);
        scale_s = fminf(1.f, 10.f / fmaxf(n, 1e-6f));
    }
    __syncthreads();
    if (tid < 64) out[b * Rq + tid] = uvec[tid] * scale_s;
}

// ---------------------------------------------------------------------------
extern "C" void kernel_launch(void* const* d_in, const int* in_sizes, int n_in,
                              void* d_out, int out_size) {
    const float* state = (const float*)d_in[0];
    const float* evk   = (const float*)d_in[1];
    const float* evv   = (const float*)d_in[2];
    const float* Wq    = (const float*)d_in[3];
    const float* Wk    = (const float*)d_in[4];
    const float* Wv    = (const float*)d_in[5];
    const float* gq    = (const float*)d_in[6];
    const float* lq    = (const float*)d_in[7];
    const int*   tok   = (const int*)d_in[8];
    float* out = (float*)d_out;

    k_prep  <<<17, 256>>>(Wk, lq);
    k_lscore<<<dim3(16, Lq, Bq), 256>>>((const float4*)evk);
    k_softL <<<1, 64>>>();
    k_qk    <<<Gq, 256>>>((const float4*)gq, (const float4*)Wq, (const float4*)Wk);
    k_weight<<<dim3(4, Eq, 4), 256>>>((const float4*)evk, (const float4*)evv);
    k_scores<<<dim3(Eq / 4, Bq), 256>>>();
    k_attn  <<<Bq, 256>>>();
    k_sh    <<<dim3(8, 4, Bq), 256>>>();
    k_final <<<Bq, 512>>>(state, (const float4*)Wv, tok, out);
}

// round 7
// speedup vs baseline: 1.7340x; 1.7340x over previous
#include <cuda_runtime.h>
#include <math.h>

// Problem constants (fixed by the dataset)
#define Bq 2
#define Lq 32
#define Eq 256
#define Hq 4096
#define Gq 16
#define Rq 64
#define H4 1024   // Hq/4 (float4 units)

// Scratch (device globals; no allocation in kernel_launch)
__device__ float g_wkq[Hq];            // Wk^T @ layer_query        [H]
__device__ float g_lscore[Bq*Lq];      // layer scores (accum)      [B,L]
__device__ float g_lw[Bq*Lq];          // layer softmax weights     [B,L]
__device__ float g_q[Gq*Rq];           // global_q @ Wq^T           [G,R]
__device__ float g_qkh[Gq*Hq];         // inv_sqrt_r * q @ Wk       [G,H]
__device__ float g_ek[Bq*Eq*Hq];       // layer-weighted k          [B,E,H]  8MB
__device__ float g_ev[Bq*Eq*Hq];       // layer-weighted v          [B,E,H]  8MB
__device__ float g_scores[Bq*Gq*Eq];   // cross-attn logits         [B,G,E]
__device__ float g_aw[Bq*Eq];          // mean_g attn               [B,E]
__device__ float g_sh[Bq*Hq];          // Σ_e aw*ev (accum)         [B,H]
__device__ float g_snew[Bq*Rq];        // projected new state       [B,R]

// ---------------------------------------------------------------------------
// K1: blocks 0..15  : wkq[h] = Σ_r Wk[r,h]*lq[r]
//     block  16     : zero the atomic accumulators
//     blocks 17..80 : q[g,r] = Σ_h gq[g,h]*Wq[r,h]  (one block per r; Wq read once)
// grid(81) x 256
__global__ void k_prep(const float* __restrict__ Wk, const float* __restrict__ lq,
                       const float4* __restrict__ gq4, const float4* __restrict__ wq4) {
    int tid = threadIdx.x;
    int bx = blockIdx.x;
    if (bx < 16) {
        __shared__ float slq[Rq];
        if (tid < Rq) slq[tid] = lq[tid];
        __syncthreads();
        int h = bx * 256 + tid;
        float s = 0.f;
        #pragma unroll
        for (int r = 0; r < Rq; ++r) s += Wk[r * Hq + h] * slq[r];
        g_wkq[h] = s;
    } else if (bx == 16) {
        if (tid < Bq * Lq) g_lscore[tid] = 0.f;
        for (int i = tid; i < Bq * Hq; i += 256) g_sh[i] = 0.f;
    } else {
        int r = bx - 17;                       // 0..63
        float4 w[4];
        #pragma unroll
        for (int j = 0; j < 4; ++j) w[j] = wq4[r * H4 + j * 256 + tid];
        float p[Gq];
        #pragma unroll
        for (int g = 0; g < Gq; ++g) {
            float s = 0.f;
            #pragma unroll
            for (int j = 0; j < 4; ++j) {
                float4 a = gq4[g * H4 + j * 256 + tid];
                s += a.x * w[j].x + a.y * w[j].y + a.z * w[j].z + a.w * w[j].w;
            }
            p[g] = s;
        }
        __shared__ float sbuf[Gq * 8];
        int lane = tid & 31, warp = tid >> 5;
        #pragma unroll
        for (int g = 0; g < Gq; ++g) {
            float v = p[g];
            #pragma unroll
            for (int o = 16; o; o >>= 1) v += __shfl_down_sync(0xffffffffu, v, o);
            if (lane == 0) sbuf[g * 8 + warp] = v;
        }
        __syncthreads();
        if (tid < Gq) {
            float s = 0.f;
            #pragma unroll
            for (int wgt = 0; wgt < 8; ++wgt) s += sbuf[tid * 8 + wgt];
            g_q[tid * Rq + r] = s;
        }
    }
}

// ---------------------------------------------------------------------------
// K2 (fused):
//   blocks x<16 : layer-score partials Σ_{e,h} evicted_k[b,l,e,h]*wkq[h] (268MB stream)
//   blocks x>=16 (z==0, y<16) : qkh[g,h] = 0.125 * Σ_r q[g,r]*Wk[r,h]  (L2-bound, overlaps)
// grid(20, L, B) x 256
__global__ void k_main1(const float4* __restrict__ evk4, const float4* __restrict__ wk4) {
    int tid = threadIdx.x;
    if (blockIdx.x < 16) {
        int e0 = blockIdx.x * 16;
        int l  = blockIdx.y;
        int b  = blockIdx.z;
        size_t base4 = ((size_t)((b * Lq + l) * Eq + e0)) * H4;
        const float4* wkq4 = (const float4*)g_wkq;
        float acc = 0.f;
        #pragma unroll 8
        for (int i = 0; i < 64; ++i) {
            int idx = i * 256 + tid;           // 0..16383 (16 rows x 1024 f4)
            float4 d = evk4[base4 + idx];
            float4 w = wkq4[idx & (H4 - 1)];
            acc += d.x * w.x + d.y * w.y + d.z * w.z + d.w * w.w;
        }
        __shared__ float red[256];
        red[tid] = acc; __syncthreads();
        #pragma unroll
        for (int s = 128; s > 0; s >>= 1) {
            if (tid < s) red[tid] += red[tid + s];
            __syncthreads();
        }
        if (tid == 0) atomicAdd(&g_lscore[b * Lq + l], red[0]);
    } else {
        if (blockIdx.z != 0 || blockIdx.y >= 16) return;
        int hc = blockIdx.x - 16;              // 0..3
        int g  = blockIdx.y;                   // 0..15
        __shared__ float sq[Rq];
        if (tid < Rq) sq[tid] = g_q[g * Rq + tid];
        __syncthreads();
        int h4 = hc * 256 + tid;
        float4 v = make_float4(0.f, 0.f, 0.f, 0.f);
        #pragma unroll 16
        for (int r = 0; r < Rq; ++r) {
            float4 w = wk4[r * H4 + h4];
            float qv = sq[r];
            v.x += qv * w.x; v.y += qv * w.y; v.z += qv * w.z; v.w += qv * w.w;
        }
        v.x *= 0.125f; v.y *= 0.125f; v.z *= 0.125f; v.w *= 0.125f;  // inv_sqrt_r
        ((float4*)g_qkh)[g * H4 + h4] = v;
    }
}

// ---------------------------------------------------------------------------
// K3: softmax over L per b. <<<1,64>>> : warp 0 -> b=0, warp 1 -> b=1.
__global__ void k_softL() {
    int tid = threadIdx.x;
    // scale = inv_sqrt_r / (LAYER_TEMP * E) = (1/8)/256
    float s = g_lscore[tid] * (1.0f / 2048.0f);
    float m = s;
    #pragma unroll
    for (int o = 16; o; o >>= 1) m = fmaxf(m, __shfl_xor_sync(0xffffffffu, m, o));
    float e = expf(s - m);
    float sum = e;
    #pragma unroll
    for (int o = 16; o; o >>= 1) sum += __shfl_xor_sync(0xffffffffu, sum, o);
    g_lw[tid] = e / sum;
}

// ---------------------------------------------------------------------------
// K4: ek/ev[b,e,h] = Σ_l w[b,l]*input[b,l,e,h]   (536 MB stream, 16 MB write)
// grid(4, E, 4) x 256; z<2 -> k (b=z), z>=2 -> v (b=z-2).
__global__ void k_weight(const float4* __restrict__ evk4,
                         const float4* __restrict__ evv4) {
    __shared__ float sw[Lq];
    int tid = threadIdx.x;
    int hc  = blockIdx.x;     // 0..3 (1024-float chunk of H)
    int e   = blockIdx.y;     // 0..255
    int z   = blockIdx.z;     // 0..3
    int b   = z & 1;
    const float4* in = (z < 2) ? evk4 : evv4;
    float4* outp = (float4*)((z < 2) ? g_ek : g_ev);
    if (tid < Lq) sw[tid] = g_lw[b * Lq + tid];
    __syncthreads();
    int off = hc * 256 + tid;                 // f4 offset within H
    const float4* p = in + ((size_t)(b * Lq) * Eq + e) * H4 + off;
    const size_t lstride = (size_t)Eq * H4;   // stride between l slices (f4)
    float4 acc = make_float4(0.f, 0.f, 0.f, 0.f);
    #pragma unroll
    for (int l = 0; l < Lq; ++l) {
        float4 d = p[l * lstride];
        float w = sw[l];
        acc.x += w * d.x; acc.y += w * d.y; acc.z += w * d.z; acc.w += w * d.w;
    }
    outp[((size_t)(b * Eq + e)) * H4 + off] = acc;
}

// ---------------------------------------------------------------------------
// K5: scores[b,g,e] = Σ_h ek[b,e,h]*qkh[g,h].  grid(E/4, B) x 256.
__global__ __launch_bounds__(256) void k_scores() {
    int tid = threadIdx.x;
    int e0 = blockIdx.x * 4;
    int b  = blockIdx.y;
    const float4* ek4 = (const float4*)g_ek;
    const float4* qk4 = (const float4*)g_qkh;
    float acc[4][16];
    #pragma unroll
    for (int j = 0; j < 4; ++j)
        #pragma unroll
        for (int g = 0; g < 16; ++g) acc[j][g] = 0.f;
    size_t rowb = ((size_t)(b * Eq + e0)) * H4;
    #pragma unroll
    for (int i = 0; i < 4; ++i) {
        int off = i * 256 + tid;
        float4 ev[4];
        #pragma unroll
        for (int j = 0; j < 4; ++j) ev[j] = ek4[rowb + j * H4 + off];
        #pragma unroll
        for (int g = 0; g < 16; ++g) {
            float4 q = qk4[g * H4 + off];
            #pragma unroll
            for (int j = 0; j < 4; ++j)
                acc[j][g] += ev[j].x * q.x + ev[j].y * q.y + ev[j].z * q.z + ev[j].w * q.w;
        }
    }
    __shared__ float sbuf[64 * 8];
    int lane = tid & 31, warp = tid >> 5;
    #pragma unroll
    for (int j = 0; j < 4; ++j)
        #pragma unroll
        for (int g = 0; g < 16; ++g) {
            float v = acc[j][g];
            #pragma unroll
            for (int o = 16; o; o >>= 1) v += __shfl_down_sync(0xffffffffu, v, o);
            if (lane == 0) sbuf[(j * 16 + g) * 8 + warp] = v;
        }
    __syncthreads();
    if (tid < 64) {
        int j = tid >> 4, g = tid & 15;
        float s = 0.f;
        #pragma unroll
        for (int w = 0; w < 8; ++w) s += sbuf[tid * 8 + w];
        g_scores[(b * Gq + g) * Eq + e0 + j] = s;
    }
}

// ---------------------------------------------------------------------------
// K6: softmax over E per (b,g) — one WARP per g; aw[b,e] = mean_g attn.
// grid(B) x 512 (16 warps = 16 g's).
__global__ void k_attn() {
    int tid = threadIdx.x;
    int b = blockIdx.x;
    int lane = tid & 31, g = tid >> 5;      // warp index == g
    __shared__ float sbuf[Gq * Eq];         // 16KB
    float s[8];
    float m = -1e30f;
    #pragma unroll
    for (int j = 0; j < 8; ++j) {
        s[j] = g_scores[(b * Gq + g) * Eq + j * 32 + lane];
        m = fmaxf(m, s[j]);
    }
    #pragma unroll
    for (int o = 16; o; o >>= 1) m = fmaxf(m, __shfl_xor_sync(0xffffffffu, m, o));
    float sum = 0.f;
    #pragma unroll
    for (int j = 0; j < 8; ++j) { s[j] = expf(s[j] - m); sum += s[j]; }
    #pragma unroll
    for (int o = 16; o; o >>= 1) sum += __shfl_xor_sync(0xffffffffu, sum, o);
    float inv = 1.0f / sum;
    #pragma unroll
    for (int j = 0; j < 8; ++j) sbuf[g * Eq + j * 32 + lane] = s[j] * inv;
    __syncthreads();
    if (tid < Eq) {
        float a = 0.f;
        #pragma unroll
        for (int gg = 0; gg < Gq; ++gg) a += sbuf[gg * Eq + tid];
        g_aw[b * Eq + tid] = a * (1.0f / (float)Gq);
    }
}

// ---------------------------------------------------------------------------
// K7: sh[b,h] += Σ_e aw[b,e]*ev[b,e,h]  (8 MB stream). grid(8,4,B) x 256.
__global__ void k_sh() {
    __shared__ float sa[32];
    int tid = threadIdx.x;
    int e0 = blockIdx.x * 32;
    int hc = blockIdx.y;
    int b  = blockIdx.z;
    if (tid < 32) sa[tid] = g_aw[b * Eq + e0 + tid];
    __syncthreads();
    const float4* ev4 = (const float4*)g_ev;
    int off = hc * 256 + tid;
    float4 acc = make_float4(0.f, 0.f, 0.f, 0.f);
    #pragma unroll
    for (int e = 0; e < 32; ++e) {
        float4 d = ev4[((size_t)(b * Eq + e0 + e)) * H4 + off];
        float a = sa[e];
        acc.x += a * d.x; acc.y += a * d.y; acc.z += a * d.z; acc.w += a * d.w;
    }
    float* shp = &g_sh[b * Hq + off * 4];
    atomicAdd(shp + 0, acc.x);
    atomicAdd(shp + 1, acc.y);
    atomicAdd(shp + 2, acc.z);
    atomicAdd(shp + 3, acc.w);
}

// ---------------------------------------------------------------------------
// K8: s_new[b,r] = Σ_h sh[b,h]*Wv[r,h] — one block per r, Wv read exactly once.
// grid(64) x 256.
__global__ void k_snew(const float4* __restrict__ wv4) {
    int tid = threadIdx.x;
    int r = blockIdx.x;
    const float4* sh4 = (const float4*)g_sh;
    float4 w[4];
    #pragma unroll
    for (int j = 0; j < 4; ++j) w[j] = wv4[r * H4 + j * 256 + tid];
    float p[Bq];
    #pragma unroll
    for (int b = 0; b < Bq; ++b) {
        float s = 0.f;
        #pragma unroll
        for (int j = 0; j < 4; ++j) {
            float4 a = sh4[b * H4 + j * 256 + tid];
            s += a.x * w[j].x + a.y * w[j].y + a.z * w[j].z + a.w * w[j].w;
        }
        p[b] = s;
    }
    __shared__ float sbuf[Bq * 8];
    int lane = tid & 31, warp = tid >> 5;
    #pragma unroll
    for (int b = 0; b < Bq; ++b) {
        float v = p[b];
        #pragma unroll
        for (int o = 16; o; o >>= 1) v += __shfl_down_sync(0xffffffffu, v, o);
        if (lane == 0) sbuf[b * 8 + warp] = v;
    }
    __syncthreads();
    if (tid < Bq) {
        float s = 0.f;
        #pragma unroll
        for (int wgt = 0; wgt < 8; ++wgt) s += sbuf[tid * 8 + wgt];
        g_snew[tid * Rq + r] = s;
    }
}

// ---------------------------------------------------------------------------
// K9: gated state update + norm clamp.  grid(1) x 128 (b = tid>>6).
__global__ void k_fin(const float* __restrict__ state,
                      const int* __restrict__ tok,
                      float* __restrict__ out) {
    int tid = threadIdx.x;        // 0..127; tid = b*64 + r
    float pv = state[tid];
    float sn = g_snew[tid];
    __shared__ float red[3 * 128];
    __shared__ float gate_s[Bq], scale_s[Bq];
    red[tid] = pv * pv; red[128 + tid] = sn * sn; red[256 + tid] = pv * sn;
    __syncthreads();
    if (tid < Bq) {
        float pp = 0.f, ss = 0.f, ps = 0.f;
        int base = tid * 64;
        for (int i = 0; i < 64; ++i) {
            pp += red[base + i]; ss += red[128 + base + i]; ps += red[256 + base + i];
        }
        float np = fmaxf(sqrtf(pp), 1e-6f);
        float ns = fmaxf(sqrtf(ss), 1e-6f);
        float sim = ps / (np * ns);
        sim = fminf(1.f, fmaxf(-1.f, sim));
        float gate = 0.1f + 0.8f * 0.5f * (sim + 1.f);
        float evd = fminf(1.f, (float)tok[0] * (1.0f / 256.0f));
        gate_s[tid] = gate * evd;
    }
    __syncthreads();
    float g = gate_s[tid >> 6];
    float u = (1.f - g) * pv + g * sn;
    red[tid] = u * u;
    __syncthreads();
    if (tid < Bq) {
        float nn = 0.f;
        int base = tid * 64;
        for (int i = 0; i < 64; ++i) nn += red[base + i];
        float n = sqrtf(nn);
        scale_s[tid] = fminf(1.f, 10.f / fmaxf(n, 1e-6f));
    }
    __syncthreads();
    out[tid] = u * scale_s[tid >> 6];
}

// ---------------------------------------------------------------------------
extern "C" void kernel_launch(void* const* d_in, const int* in_sizes, int n_in,
                              void* d_out, int out_size) {
    const float* state = (const float*)d_in[0];
    const float* evk   = (const float*)d_in[1];
    const float* evv   = (const float*)d_in[2];
    const float* Wq    = (const float*)d_in[3];
    const float* Wk    = (const float*)d_in[4];
    const float* Wv    = (const float*)d_in[5];
    const float* gq    = (const float*)d_in[6];
    const float* lq    = (const float*)d_in[7];
    const int*   tok   = (const int*)d_in[8];
    float* out = (float*)d_out;

    k_prep  <<<81, 256>>>(Wk, lq, (const float4*)gq, (const float4*)Wq);
    k_main1 <<<dim3(20, Lq, Bq), 256>>>((const float4*)evk, (const float4*)Wk);
    k_softL <<<1, 64>>>();
    k_weight<<<dim3(4, Eq, 4), 256>>>((const float4*)evk, (const float4*)evv);
    k_scores<<<dim3(Eq / 4, Bq), 256>>>();
    k_attn  <<<Bq, 512>>>();
    k_sh    <<<dim3(8, 4, Bq), 256>>>();
    k_snew  <<<Rq, 256>>>((const float4*)Wv);
    k_fin   <<<1, 128>>>(state, tok, out);
}

// round 8
// speedup vs baseline: 1.7415x; 1.0044x over previous
#include <cuda_runtime.h>
#include <math.h>

// Problem constants (fixed by the dataset)
#define Bq 2
#define Lq 32
#define Eq 256
#define Hq 4096
#define Gq 16
#define Rq 64
#define H4 1024   // Hq/4 (float4 units)

// Scratch (device globals; no allocation in kernel_launch)
__device__ float g_wkq[Hq];            // Wk^T @ layer_query        [H]
__device__ float g_lscore[Bq*Lq];      // layer scores (accum)      [B,L]
__device__ float g_lw[Bq*Lq];          // layer softmax weights     [B,L]
__device__ float g_q[Gq*Rq];           // global_q @ Wq^T           [G,R]
__device__ float g_qkh[Gq*Hq];         // inv_sqrt_r * q @ Wk       [G,H]
__device__ float g_ek[Bq*Eq*Hq];       // layer-weighted k          [B,E,H]  8MB
__device__ float g_ev[Bq*Eq*Hq];       // layer-weighted v          [B,E,H]  8MB
__device__ float g_scores[Bq*Gq*Eq];   // cross-attn logits         [B,G,E]
__device__ float g_aw[Bq*Eq];          // mean_g attn               [B,E]
__device__ float g_sh[Bq*Hq];          // Σ_e aw*ev (accum)         [B,H]
__device__ float g_snew[Bq*Rq];        // projected new state       [B,R]

// ---------------------------------------------------------------------------
// K1: blocks 0..15  : wkq[h] = Σ_r Wk[r,h]*lq[r]
//     block  16     : zero the atomic accumulators
//     blocks 17..80 : q[g,r] = Σ_h gq[g,h]*Wq[r,h]  (one block per r; Wq read once)
// grid(81) x 256
__global__ void k_prep(const float* __restrict__ Wk, const float* __restrict__ lq,
                       const float4* __restrict__ gq4, const float4* __restrict__ wq4) {
    int tid = threadIdx.x;
    int bx = blockIdx.x;
    if (bx < 16) {
        __shared__ float slq[Rq];
        if (tid < Rq) slq[tid] = lq[tid];
        __syncthreads();
        int h = bx * 256 + tid;
        float s = 0.f;
        #pragma unroll
        for (int r = 0; r < Rq; ++r) s += Wk[r * Hq + h] * slq[r];
        g_wkq[h] = s;
    } else if (bx == 16) {
        if (tid < Bq * Lq) g_lscore[tid] = 0.f;
        for (int i = tid; i < Bq * Hq; i += 256) g_sh[i] = 0.f;
    } else {
        int r = bx - 17;                       // 0..63
        float4 w[4];
        #pragma unroll
        for (int j = 0; j < 4; ++j) w[j] = wq4[r * H4 + j * 256 + tid];
        float p[Gq];
        #pragma unroll
        for (int g = 0; g < Gq; ++g) {
            float s = 0.f;
            #pragma unroll
            for (int j = 0; j < 4; ++j) {
                float4 a = gq4[g * H4 + j * 256 + tid];
                s += a.x * w[j].x + a.y * w[j].y + a.z * w[j].z + a.w * w[j].w;
            }
            p[g] = s;
        }
        __shared__ float sbuf[Gq * 8];
        int lane = tid & 31, warp = tid >> 5;
        #pragma unroll
        for (int g = 0; g < Gq; ++g) {
            float v = p[g];
            #pragma unroll
            for (int o = 16; o; o >>= 1) v += __shfl_down_sync(0xffffffffu, v, o);
            if (lane == 0) sbuf[g * 8 + warp] = v;
        }
        __syncthreads();
        if (tid < Gq) {
            float s = 0.f;
            #pragma unroll
            for (int wgt = 0; wgt < 8; ++wgt) s += sbuf[tid * 8 + wgt];
            g_q[tid * Rq + r] = s;
        }
    }
}

// ---------------------------------------------------------------------------
// K2 (fused):
//   blocks x<16 : layer-score partials Σ_{e,h} evicted_k[b,l,e,h]*wkq[h] (268MB stream)
//   blocks x>=16 (z==0, y<16) : qkh[g,h] = 0.125 * Σ_r q[g,r]*Wk[r,h]  (L2-bound, overlaps)
// grid(20, L, B) x 256
__global__ void k_main1(const float4* __restrict__ evk4, const float4* __restrict__ wk4) {
    int tid = threadIdx.x;
    if (blockIdx.x < 16) {
        int e0 = blockIdx.x * 16;
        int l  = blockIdx.y;
        int b  = blockIdx.z;
        size_t base4 = ((size_t)((b * Lq + l) * Eq + e0)) * H4;
        const float4* wkq4 = (const float4*)g_wkq;
        float acc = 0.f;
        #pragma unroll 8
        for (int i = 0; i < 64; ++i) {
            int idx = i * 256 + tid;           // 0..16383 (16 rows x 1024 f4)
            float4 d = evk4[base4 + idx];
            float4 w = wkq4[idx & (H4 - 1)];
            acc += d.x * w.x + d.y * w.y + d.z * w.z + d.w * w.w;
        }
        __shared__ float red[256];
        red[tid] = acc; __syncthreads();
        #pragma unroll
        for (int s = 128; s > 0; s >>= 1) {
            if (tid < s) red[tid] += red[tid + s];
            __syncthreads();
        }
        if (tid == 0) atomicAdd(&g_lscore[b * Lq + l], red[0]);
    } else {
        if (blockIdx.z != 0 || blockIdx.y >= 16) return;
        int hc = blockIdx.x - 16;              // 0..3
        int g  = blockIdx.y;                   // 0..15
        __shared__ float sq[Rq];
        if (tid < Rq) sq[tid] = g_q[g * Rq + tid];
        __syncthreads();
        int h4 = hc * 256 + tid;
        float4 v = make_float4(0.f, 0.f, 0.f, 0.f);
        #pragma unroll 16
        for (int r = 0; r < Rq; ++r) {
            float4 w = wk4[r * H4 + h4];
            float qv = sq[r];
            v.x += qv * w.x; v.y += qv * w.y; v.z += qv * w.z; v.w += qv * w.w;
        }
        v.x *= 0.125f; v.y *= 0.125f; v.z *= 0.125f; v.w *= 0.125f;  // inv_sqrt_r
        ((float4*)g_qkh)[g * H4 + h4] = v;
    }
}

// ---------------------------------------------------------------------------
// K3: softmax over L per b. <<<1,64>>> : warp 0 -> b=0, warp 1 -> b=1.
__global__ void k_softL() {
    int tid = threadIdx.x;
    // scale = inv_sqrt_r / (LAYER_TEMP * E) = (1/8)/256
    float s = g_lscore[tid] * (1.0f / 2048.0f);
    float m = s;
    #pragma unroll
    for (int o = 16; o; o >>= 1) m = fmaxf(m, __shfl_xor_sync(0xffffffffu, m, o));
    float e = expf(s - m);
    float sum = e;
    #pragma unroll
    for (int o = 16; o; o >>= 1) sum += __shfl_xor_sync(0xffffffffu, sum, o);
    g_lw[tid] = e / sum;
}

// ---------------------------------------------------------------------------
// K4: ek/ev[b,e,h] = Σ_l w[b,l]*input[b,l,e,h]   (536 MB stream, 16 MB write)
// grid(4, E, 4) x 256; z<2 -> k (b=z), z>=2 -> v (b=z-2).
__global__ void k_weight(const float4* __restrict__ evk4,
                         const float4* __restrict__ evv4) {
    __shared__ float sw[Lq];
    int tid = threadIdx.x;
    int hc  = blockIdx.x;     // 0..3 (1024-float chunk of H)
    int e   = blockIdx.y;     // 0..255
    int z   = blockIdx.z;     // 0..3
    int b   = z & 1;
    const float4* in = (z < 2) ? evk4 : evv4;
    float4* outp = (float4*)((z < 2) ? g_ek : g_ev);
    if (tid < Lq) sw[tid] = g_lw[b * Lq + tid];
    __syncthreads();
    int off = hc * 256 + tid;                 // f4 offset within H
    const float4* p = in + ((size_t)(b * Lq) * Eq + e) * H4 + off;
    const size_t lstride = (size_t)Eq * H4;   // stride between l slices (f4)
    float4 acc = make_float4(0.f, 0.f, 0.f, 0.f);
    #pragma unroll
    for (int l = 0; l < Lq; ++l) {
        float4 d = p[l * lstride];
        float w = sw[l];
        acc.x += w * d.x; acc.y += w * d.y; acc.z += w * d.z; acc.w += w * d.w;
    }
    outp[((size_t)(b * Eq + e)) * H4 + off] = acc;
}

// ---------------------------------------------------------------------------
// K5: scores[b,g,e] = Σ_h ek[b,e,h]*qkh[g,h].  grid(E/4, B) x 256.
__global__ __launch_bounds__(256) void k_scores() {
    int tid = threadIdx.x;
    int e0 = blockIdx.x * 4;
    int b  = blockIdx.y;
    const float4* ek4 = (const float4*)g_ek;
    const float4* qk4 = (const float4*)g_qkh;
    float acc[4][16];
    #pragma unroll
    for (int j = 0; j < 4; ++j)
        #pragma unroll
        for (int g = 0; g < 16; ++g) acc[j][g] = 0.f;
    size_t rowb = ((size_t)(b * Eq + e0)) * H4;
    #pragma unroll
    for (int i = 0; i < 4; ++i) {
        int off = i * 256 + tid;
        float4 ev[4];
        #pragma unroll
        for (int j = 0; j < 4; ++j) ev[j] = ek4[rowb + j * H4 + off];
        #pragma unroll
        for (int g = 0; g < 16; ++g) {
            float4 q = qk4[g * H4 + off];
            #pragma unroll
            for (int j = 0; j < 4; ++j)
                acc[j][g] += ev[j].x * q.x + ev[j].y * q.y + ev[j].z * q.z + ev[j].w * q.w;
        }
    }
    __shared__ float sbuf[64 * 8];
    int lane = tid & 31, warp = tid >> 5;
    #pragma unroll
    for (int j = 0; j < 4; ++j)
        #pragma unroll
        for (int g = 0; g < 16; ++g) {
            float v = acc[j][g];
            #pragma unroll
            for (int o = 16; o; o >>= 1) v += __shfl_down_sync(0xffffffffu, v, o);
            if (lane == 0) sbuf[(j * 16 + g) * 8 + warp] = v;
        }
    __syncthreads();
    if (tid < 64) {
        int j = tid >> 4, g = tid & 15;
        float s = 0.f;
        #pragma unroll
        for (int w = 0; w < 8; ++w) s += sbuf[tid * 8 + w];
        g_scores[(b * Gq + g) * Eq + e0 + j] = s;
    }
}

// ---------------------------------------------------------------------------
// K6: softmax over E per (b,g) — one WARP per g; aw[b,e] = mean_g attn.
// grid(B) x 512 (16 warps = 16 g's).
__global__ void k_attn() {
    int tid = threadIdx.x;
    int b = blockIdx.x;
    int lane = tid & 31, g = tid >> 5;      // warp index == g
    __shared__ float sbuf[Gq * Eq];         // 16KB
    float s[8];
    float m = -1e30f;
    #pragma unroll
    for (int j = 0; j < 8; ++j) {
        s[j] = g_scores[(b * Gq + g) * Eq + j * 32 + lane];
        m = fmaxf(m, s[j]);
    }
    #pragma unroll
    for (int o = 16; o; o >>= 1) m = fmaxf(m, __shfl_xor_sync(0xffffffffu, m, o));
    float sum = 0.f;
    #pragma unroll
    for (int j = 0; j < 8; ++j) { s[j] = expf(s[j] - m); sum += s[j]; }
    #pragma unroll
    for (int o = 16; o; o >>= 1) sum += __shfl_xor_sync(0xffffffffu, sum, o);
    float inv = 1.0f / sum;
    #pragma unroll
    for (int j = 0; j < 8; ++j) sbuf[g * Eq + j * 32 + lane] = s[j] * inv;
    __syncthreads();
    if (tid < Eq) {
        float a = 0.f;
        #pragma unroll
        for (int gg = 0; gg < Gq; ++gg) a += sbuf[gg * Eq + tid];
        g_aw[b * Eq + tid] = a * (1.0f / (float)Gq);
    }
}

// ---------------------------------------------------------------------------
// K7: sh[b,h] += Σ_e aw[b,e]*ev[b,e,h]  (8 MB stream). grid(8,4,B) x 256.
__global__ void k_sh() {
    __shared__ float sa[32];
    int tid = threadIdx.x;
    int e0 = blockIdx.x * 32;
    int hc = blockIdx.y;
    int b  = blockIdx.z;
    if (tid < 32) sa[tid] = g_aw[b * Eq + e0 + tid];
    __syncthreads();
    const float4* ev4 = (const float4*)g_ev;
    int off = hc * 256 + tid;
    float4 acc = make_float4(0.f, 0.f, 0.f, 0.f);
    #pragma unroll
    for (int e = 0; e < 32; ++e) {
        float4 d = ev4[((size_t)(b * Eq + e0 + e)) * H4 + off];
        float a = sa[e];
        acc.x += a * d.x; acc.y += a * d.y; acc.z += a * d.z; acc.w += a * d.w;
    }
    float* shp = &g_sh[b * Hq + off * 4];
    atomicAdd(shp + 0, acc.x);
    atomicAdd(shp + 1, acc.y);
    atomicAdd(shp + 2, acc.z);
    atomicAdd(shp + 3, acc.w);
}

// ---------------------------------------------------------------------------
// K8: s_new[b,r] = Σ_h sh[b,h]*Wv[r,h] — one block per r, Wv read exactly once.
// grid(64) x 256.
__global__ void k_snew(const float4* __restrict__ wv4) {
    int tid = threadIdx.x;
    int r = blockIdx.x;
    const float4* sh4 = (const float4*)g_sh;
    float4 w[4];
    #pragma unroll
    for (int j = 0; j < 4; ++j) w[j] = wv4[r * H4 + j * 256 + tid];
    float p[Bq];
    #pragma unroll
    for (int b = 0; b < Bq; ++b) {
        float s = 0.f;
        #pragma unroll
        for (int j = 0; j < 4; ++j) {
            float4 a = sh4[b * H4 + j * 256 + tid];
            s += a.x * w[j].x + a.y * w[j].y + a.z * w[j].z + a.w * w[j].w;
        }
        p[b] = s;
    }
    __shared__ float sbuf[Bq * 8];
    int lane = tid & 31, warp = tid >> 5;
    #pragma unroll
    for (int b = 0; b < Bq; ++b) {
        float v = p[b];
        #pragma unroll
        for (int o = 16; o; o >>= 1) v += __shfl_down_sync(0xffffffffu, v, o);
        if (lane == 0) sbuf[b * 8 + warp] = v;
    }
    __syncthreads();
    if (tid < Bq) {
        float s = 0.f;
        #pragma unroll
        for (int wgt = 0; wgt < 8; ++wgt) s += sbuf[tid * 8 + wgt];
        g_snew[tid * Rq + r] = s;
    }
}

// ---------------------------------------------------------------------------
// K9: gated state update + norm clamp.  grid(1) x 128 (b = tid>>6).
__global__ void k_fin(const float* __restrict__ state,
                      const int* __restrict__ tok,
                      float* __restrict__ out) {
    int tid = threadIdx.x;        // 0..127; tid = b*64 + r
    float pv = state[tid];
    float sn = g_snew[tid];
    __shared__ float red[3 * 128];
    __shared__ float gate_s[Bq], scale_s[Bq];
    red[tid] = pv * pv; red[128 + tid] = sn * sn; red[256 + tid] = pv * sn;
    __syncthreads();
    if (tid < Bq) {
        float pp = 0.f, ss = 0.f, ps = 0.f;
        int base = tid * 64;
        for (int i = 0; i < 64; ++i) {
            pp += red[base + i]; ss += red[128 + base + i]; ps += red[256 + base + i];
        }
        float np = fmaxf(sqrtf(pp), 1e-6f);
        float ns = fmaxf(sqrtf(ss), 1e-6f);
        float sim = ps / (np * ns);
        sim = fminf(1.f, fmaxf(-1.f, sim));
        float gate = 0.1f + 0.8f * 0.5f * (sim + 1.f);
        float evd = fminf(1.f, (float)tok[0] * (1.0f / 256.0f));
        gate_s[tid] = gate * evd;
    }
    __syncthreads();
    float g = gate_s[tid >> 6];
    float u = (1.f - g) * pv + g * sn;
    red[tid] = u * u;
    __syncthreads();
    if (tid < Bq) {
        float nn = 0.f;
        int base = tid * 64;
        for (int i = 0; i < 64; ++i) nn += red[base + i];
        float n = sqrtf(nn);
        scale_s[tid] = fminf(1.f, 10.f / fmaxf(n, 1e-6f));
    }
    __syncthreads();
    out[tid] = u * scale_s[tid >> 6];
}

// ---------------------------------------------------------------------------
extern "C" void kernel_launch(void* const* d_in, const int* in_sizes, int n_in,
                              void* d_out, int out_size) {
    const float* state = (const float*)d_in[0];
    const float* evk   = (const float*)d_in[1];
    const float* evv   = (const float*)d_in[2];
    const float* Wq    = (const float*)d_in[3];
    const float* Wk    = (const float*)d_in[4];
    const float* Wv    = (const float*)d_in[5];
    const float* gq    = (const float*)d_in[6];
    const float* lq    = (const float*)d_in[7];
    const int*   tok   = (const int*)d_in[8];
    float* out = (float*)d_out;

    k_prep  <<<81, 256>>>(Wk, lq, (const float4*)gq, (const float4*)Wq);
    k_main1 <<<dim3(20, Lq, Bq), 256>>>((const float4*)evk, (const float4*)Wk);
    k_softL <<<1, 64>>>();
    k_weight<<<dim3(4, Eq, 4), 256>>>((const float4*)evk, (const float4*)evv);
    k_scores<<<dim3(Eq / 4, Bq), 256>>>();
    k_attn  <<<Bq, 512>>>();
    k_sh    <<<dim3(8, 4, Bq), 256>>>();
    k_snew  <<<Rq, 256>>>((const float4*)Wv);
    k_fin   <<<1, 128>>>(state, tok, out);
}